// round 13
// baseline (speedup 1.0000x reference)
#include <cuda_runtime.h>
#include <cuda_fp16.h>
#include <math.h>
#include <stdint.h>

#define NB 512
#define SS 128
#define TT 128
#define EE 128
#define HH 1024
#define VV 128
#define G3 (3*HH)

#define BM 128                     // batch rows per block
#define HCOL 32                    // h-columns per block
#define BNR 96                     // B rows per block (3 gates x 32)
#define KS 64
#define NCHUNK (HH/KS)             // 16
#define THREADS 384
#define TA_HALFS (BM*KS)           // 8192 per plane
#define TB_HALFS (BNR*KS)          // 6144 per plane
#define TA_BYTES (TA_HALFS*2)      // 16384
#define TB_BYTES (TB_HALFS*2)      // 12288
#define STAGE_BYTES (2*TA_BYTES + 2*TB_BYTES)   // 57344
#define NSTAGE 3
#define SMEM_DYN (NSTAGE*STAGE_BYTES)           // 172032
#define GHS_PITCH 100              // fp32 pitch for epilogue exchange

#define P1 (1.0f/2048.0f)
#define S1 2048.0f

// ================= device scratch =================
__device__ float g_h[2][NB*HH];                           // fp32 hidden master
__device__ __align__(16) __half g_hP[2][2][NB*HH];        // h planes, 128x64 A-tile layout
__device__ __align__(16) __half g_WP[2][2][(size_t)G3*HH];// Whh planes, gate-interleaved B-tiles
__device__ float g_Gsrc[VV*G3];
__device__ float g_Gtrg[VV*G3];
__device__ int   g_tok[NB];
__device__ float g_pred_part[8][NB*VV];

// ================= PTX helpers (portable) =================
__device__ __forceinline__ uint32_t smem_u32(const void* p) {
    uint32_t a;
    asm("{ .reg .u64 t; cvta.to.shared.u64 t, %1; cvt.u32.u64 %0, t; }" : "=r"(a) : "l"(p));
    return a;
}
#define CP16(sm, gp) \
    asm volatile("cp.async.cg.shared.global [%0], [%1], 16;" :: "r"(sm), "l"(gp) : "memory")
#define CP_COMMIT() asm volatile("cp.async.commit_group;" ::: "memory")
#define CP_WAIT1()  asm volatile("cp.async.wait_group 1;" ::: "memory")
#define CP_WAIT0()  asm volatile("cp.async.wait_group 0;" ::: "memory")
#define LDSM4(r, a) \
    asm volatile("ldmatrix.sync.aligned.m8n8.x4.shared.b16 {%0,%1,%2,%3}, [%4];" \
        : "=r"((r)[0]),"=r"((r)[1]),"=r"((r)[2]),"=r"((r)[3]) : "r"(a))
// chained MMA (in-HMMA accumulate)
#define MMA16816(d, a, b0, b1) \
    asm volatile("mma.sync.aligned.m16n8k16.row.col.f32.f16.f16.f32 " \
        "{%0,%1,%2,%3}, {%4,%5,%6,%7}, {%8,%9}, {%0,%1,%2,%3};" \
        : "+f"((d)[0]),"+f"((d)[1]),"+f"((d)[2]),"+f"((d)[3]) \
        : "r"((a)[0]),"r"((a)[1]),"r"((a)[2]),"r"((a)[3]), "r"(b0),"r"(b1))
// zero-C MMA: fresh outputs, no in-HMMA chaining
#define MMA16816_Z(d, a, b0, b1) \
    asm volatile("mma.sync.aligned.m16n8k16.row.col.f32.f16.f16.f32 " \
        "{%0,%1,%2,%3}, {%4,%5,%6,%7}, {%8,%9}, {%10,%10,%10,%10};" \
        : "=f"((d)[0]),"=f"((d)[1]),"=f"((d)[2]),"=f"((d)[3]) \
        : "r"((a)[0]),"r"((a)[1]),"r"((a)[2]),"r"((a)[3]), "r"(b0),"r"(b1), "f"(0.0f))

// swizzled half index within a tile (row pitch 128B; 16B chunk ^= row&7)
__device__ __forceinline__ int sw_half(int r, int c) {
    return r*64 + (((c>>3) ^ (r&7))<<3) + (c&7);
}
__device__ __forceinline__ uint32_t ldsm_addr(uint32_t tbase, int row, int kc) {
    return tbase + row*128 + ((((kc>>3) ^ (row&7))&7)<<4);
}
// exact 2-plane fp16 split (lo scaled by 2048 into normal range)
__device__ __forceinline__ void split2(float v, __half& h0, __half& h1) {
    h0 = __float2half(v);
    float r1 = v - __half2float(h0);
    h1 = __float2half(r1 * S1);
}

// ================= build: gi tables =================
__global__ void build_tables(const float* __restrict__ emb_src,
                             const float* __restrict__ enc_Wih,
                             const float* __restrict__ enc_bih,
                             const float* __restrict__ emb_trg,
                             const float* __restrict__ dec_Wih,
                             const float* __restrict__ dec_bih)
{
    int idx = blockIdx.x * blockDim.x + threadIdx.x;
    int which = idx / (VV*G3);
    int rem   = idx % (VV*G3);
    int v = rem / G3;
    int c = rem % G3;
    const float* emb = which ? emb_trg : emb_src;
    const float* W   = which ? dec_Wih : enc_Wih;
    const float* bi  = which ? dec_bih : enc_bih;
    float s = bi[c];
    if (v != 0) {
        const float* e = emb + v*EE;
        const float* w = W + c*EE;
        #pragma unroll 8
        for (int k = 0; k < EE; k++) s += e[k]*w[k];
    }
    float* G = which ? g_Gtrg : g_Gsrc;
    G[v*G3 + c] = s;
}

// ===== build: Whh 2-plane split, gate-interleaved B-tile layout =====
__global__ void build_wsplit(const float* __restrict__ enc_Whh,
                             const float* __restrict__ dec_Whh)
{
    int idx = blockIdx.x * blockDim.x + threadIdx.x;   // 2*3072*1024
    int dir = idx / (G3*HH);
    int rem = idx % (G3*HH);
    int n = rem / HH;          // Whh row: gate*1024 + h
    int k = rem % HH;
    const float* W = dir ? dec_Whh : enc_Whh;
    float v = W[n*HH + k];
    __half h0, h1;
    split2(v, h0, h1);
    int gate = n >> 10;
    int h    = n & 1023;
    int nt   = h >> 5;
    int trow = gate*32 + (h & 31);
    size_t pos = ((size_t)nt*NCHUNK + (k >> 6))*TB_HALFS + sw_half(trow, k & 63);
    g_WP[dir][0][pos] = h0;
    g_WP[dir][1][pos] = h1;
}

// ================= init =================
__global__ void init_kernel(float* __restrict__ out, const int* __restrict__ trg)
{
    int i = blockIdx.x * blockDim.x + threadIdx.x;
    if (i < NB*HH) {
        g_h[0][i] = 0.0f;
        g_hP[0][0][i] = __float2half(0.0f);
        g_hP[0][1][i] = __float2half(0.0f);
    }
    if (i < NB*VV) {
        int b = i / VV, v = i % VV;
        out[b*(TT*VV) + v] = 0.0f;
    }
    if (i < NB) g_tok[i] = trg[i*TT];
}

// ====== fused GRU step: gate-triple tensor GEMM + gate epilogue ======
// grid (32, 4). 384 threads (12 warps as 4m x 3n; warp tile 32m x 32 B-rows).
// 170 regs/thread budget; main term pair-chained (Z + 1 chained MMA + FADD).
__global__ __launch_bounds__(THREADS, 1)
void gru_gemm(int pin, int dir, int table_sel,
              const int* __restrict__ ext_tok, int tok_stride,
              const float* __restrict__ bhh)
{
    extern __shared__ char smc[];
    const uint32_t sbase = smem_u32(smc);
    const int tid  = threadIdx.x;
    const int wid  = tid >> 5;
    const int lane = tid & 31;
    const int nt = blockIdx.x;           // h-col tile
    const int mt = blockIdx.y;           // m tile
    const int wm  = (wid >> 2) * 32 + (wid & 1) * 16; // hmm see below
    // 12 warps -> 4m x 3n: m-group = wid/3 (0..3), n-group = wid%3 (0..2)
    const int mg = wid / 3;
    const int ng = wid - mg*3;
    const int wmo = mg * 32;             // warp m offset: 0/32/64/96
    const int wno = ng * 32;             // warp B-row offset: 0/32/64

    const char* gA0 = (const char*)g_hP[pin][0] + (size_t)mt*NCHUNK*TA_BYTES;
    const char* gA1 = (const char*)g_hP[pin][1] + (size_t)mt*NCHUNK*TA_BYTES;
    const char* gB0 = (const char*)g_WP[dir][0] + (size_t)nt*NCHUNK*TB_BYTES;
    const char* gB1 = (const char*)g_WP[dir][1] + (size_t)nt*NCHUNK*TB_BYTES;

    float acc0[2][4][4], acc1[2][4][4];  // [mi][t*2+s][4]
    #pragma unroll
    for (int i = 0; i < 2; i++)
        #pragma unroll
        for (int j = 0; j < 4; j++)
            #pragma unroll
            for (int q = 0; q < 4; q++) { acc0[i][j][q] = 0.0f; acc1[i][j][q] = 0.0f; }

    // ---- cp.async issue: A 2048 lines, B 1536 lines (16B each) ----
    #define ISSUE_CHUNK(cc, buf) do {                                        \
        uint32_t sb = sbase + (buf)*STAGE_BYTES;                             \
        size_t goA = (size_t)(cc) * TA_BYTES;                                \
        size_t goB = (size_t)(cc) * TB_BYTES;                                \
        _Pragma("unroll")                                                    \
        for (int j = 0; j < 6; j++) {                                        \
            int u = tid + THREADS*j;                                         \
            if (u < 2048) {                                                  \
                int pl = u >> 10;                                            \
                int ln = u & 1023;                                           \
                const char* src = (pl ? gA1 : gA0) + goA + ln*16;            \
                CP16(sb + pl*TA_BYTES + ln*16, src);                         \
            }                                                                \
        }                                                                    \
        _Pragma("unroll")                                                    \
        for (int j = 0; j < 4; j++) {                                        \
            int u = tid + THREADS*j;             /* 0..1535 exact */         \
            int pl = (u >= 768);                                             \
            int ln = u - pl*768;                                             \
            const char* src = (pl ? gB1 : gB0) + goB + ln*16;                \
            CP16(sb + 2*TA_BYTES + pl*TB_BYTES + ln*16, src);                \
        }                                                                    \
        CP_COMMIT();                                                         \
    } while (0)

    ISSUE_CHUNK(0, 0);
    ISSUE_CHUNK(1, 1);

    const int arow  = lane & 15;
    const int khalf = (lane >> 4) * 8;

    int rbuf = 0;
    for (int c = 0; c < NCHUNK; c++) {
        if (c < NCHUNK-1) { CP_WAIT1(); } else { CP_WAIT0(); }
        __syncthreads();

        const uint32_t St = sbase + rbuf*STAGE_BYTES;
        const uint32_t A0 = St;
        const uint32_t A1 = St + TA_BYTES;
        const uint32_t B0 = St + 2*TA_BYTES;
        const uint32_t B1 = B0 + TB_BYTES;

        #pragma unroll
        for (int p = 0; p < 2; p++) {            // k16-pairs: ks = 2p, 2p+1
            uint32_t a0f[2][2][4], a1f[2][2][4]; // [kk][mi][4]
            uint32_t b0f[2][2][4], b1f[2][2][4]; // [kk][t][4]
            #pragma unroll
            for (int kk = 0; kk < 2; kk++) {
                const int kc = (2*p + kk)*16 + khalf;
                #pragma unroll
                for (int mi = 0; mi < 2; mi++) {
                    int row = wmo + mi*16 + arow;
                    LDSM4(a0f[kk][mi], ldsm_addr(A0, row, kc));
                    LDSM4(a1f[kk][mi], ldsm_addr(A1, row, kc));
                }
                #pragma unroll
                for (int t = 0; t < 2; t++) {
                    int row = wno + t*16 + arow;
                    LDSM4(b0f[kk][t], ldsm_addr(B0, row, kc));
                    LDSM4(b1f[kk][t], ldsm_addr(B1, row, kc));
                }
            }
            #pragma unroll
            for (int mi = 0; mi < 2; mi++)
                #pragma unroll
                for (int t = 0; t < 2; t++)
                    #pragma unroll
                    for (int s = 0; s < 2; s++) {
                        const int n8 = t*2 + s;
                        // main term: Z then one chained MMA (k-pair), then RN FADD
                        float dt[4];
                        MMA16816_Z(dt, a0f[0][mi], b0f[0][t][s], b0f[0][t][2+s]);
                        MMA16816(dt,  a0f[1][mi], b0f[1][t][s], b0f[1][t][2+s]);
                        acc0[mi][n8][0] += dt[0];
                        acc0[mi][n8][1] += dt[1];
                        acc0[mi][n8][2] += dt[2];
                        acc0[mi][n8][3] += dt[3];
                        // 2^-11-scaled cross terms (chained into acc1)
                        MMA16816(acc1[mi][n8], a0f[0][mi], b1f[0][t][s], b1f[0][t][2+s]);
                        MMA16816(acc1[mi][n8], a1f[0][mi], b0f[0][t][s], b0f[0][t][2+s]);
                        MMA16816(acc1[mi][n8], a0f[1][mi], b1f[1][t][s], b1f[1][t][2+s]);
                        MMA16816(acc1[mi][n8], a1f[1][mi], b0f[1][t][s], b0f[1][t][2+s]);
                    }
        }

        if (c + 2 < NCHUNK) {
            int wbuf = rbuf + 2; if (wbuf >= 3) wbuf -= 3;
            ISSUE_CHUNK(c+2, wbuf);
        }
        rbuf = (rbuf == 2) ? 0 : rbuf + 1;
    }
    #undef ISSUE_CHUNK

    // ---- epilogue part 1: gh -> smem exchange ----
    __syncthreads();
    float* ghs = (float*)smc;            // 128 x GHS_PITCH fp32 (51.2KB)
    #pragma unroll
    for (int mi = 0; mi < 2; mi++) {
        int erow = wmo + mi*16 + (lane >> 2);
        #pragma unroll
        for (int n8 = 0; n8 < 4; n8++) {
            int col = wno + n8*8 + (lane & 3)*2;
            ghs[erow*GHS_PITCH + col]         = acc0[mi][n8][0] + acc1[mi][n8][0]*P1;
            ghs[erow*GHS_PITCH + col + 1]     = acc0[mi][n8][1] + acc1[mi][n8][1]*P1;
            ghs[(erow+8)*GHS_PITCH + col]     = acc0[mi][n8][2] + acc1[mi][n8][2]*P1;
            ghs[(erow+8)*GHS_PITCH + col + 1] = acc0[mi][n8][3] + acc1[mi][n8][3]*P1;
        }
    }
    __syncthreads();

    // ---- epilogue part 2: gate math + h/plane writeback ----
    const float* __restrict__ G  = table_sel ? g_Gtrg : g_Gsrc;
    const int* __restrict__ tokp = ext_tok ? ext_tok : g_tok;
    #pragma unroll
    for (int q = 0; q < 11; q++) {
        int idx = tid + THREADS*q;       // 0..4223
        if (idx < 4096) {
            int row = idx >> 5;          // 0..127
            int hc  = idx & 31;          // 0..31
            int col  = nt*32 + hc;
            int rowg = mt*BM + row;
            int tok = tokp[rowg * tok_stride];
            const float* Grow = G + (size_t)tok*G3;

            float vr = ghs[row*GHS_PITCH + hc];
            float vz = ghs[row*GHS_PITCH + 32 + hc];
            float vn = ghs[row*GHS_PITCH + 64 + hc];
            float gr = vr + bhh[col];
            float gz = vz + bhh[HH + col];
            float gn = vn + bhh[2*HH + col];
            float r = 1.0f / (1.0f + expf(-(Grow[col]      + gr)));
            float z = 1.0f / (1.0f + expf(-(Grow[HH + col] + gz)));
            float n = tanhf(Grow[2*HH + col] + r * gn);
            float hp = g_h[pin][rowg*HH + col];
            float ho = (1.0f - z)*n + z*hp;

            g_h[pin ^ 1][rowg*HH + col] = ho;
            __half h0, h1;
            split2(ho, h0, h1);
            size_t pos = ((size_t)(rowg >> 7)*NCHUNK + (col >> 6))*TA_HALFS
                       + sw_half(rowg & 127, col & 63);
            g_hP[pin ^ 1][0][pos] = h0;
            g_hP[pin ^ 1][1][pos] = h1;
        }
    }
}

// ================= decoder pred GEMM (split-K SIMT, fp32) =================
#define PBM 32
#define PBK 16
__global__ __launch_bounds__(256, 1)
void pred_part(int pcur, const float* __restrict__ fcW)
{
    const float* __restrict__ h = g_h[pcur];
    __shared__ float As[PBK][PBM+4];
    __shared__ float Bs[PBK][VV+4];

    const int row0 = blockIdx.x * PBM;
    const int k0   = blockIdx.y * (HH/8);
    const int tx = threadIdx.x, ty = threadIdx.y;
    const int tid = ty*32 + tx;

    float acc[4][4];
    #pragma unroll
    for (int i = 0; i < 4; i++)
        #pragma unroll
        for (int j = 0; j < 4; j++) acc[i][j] = 0.0f;

    for (int kt = 0; kt < HH/8; kt += PBK) {
        if (tid < 128) {
            int ar = tid >> 2;
            int ak = (tid & 3) << 2;
            float4 av = *(const float4*)&h[(row0+ar)*HH + k0 + kt + ak];
            As[ak+0][ar] = av.x; As[ak+1][ar] = av.y;
            As[ak+2][ar] = av.z; As[ak+3][ar] = av.w;
        }
        #pragma unroll
        for (int l = 0; l < 2; l++) {
            int t2 = l*256 + tid;
            int bc = t2 >> 2;
            int bk = (t2 & 3) << 2;
            float4 bv = *(const float4*)&fcW[bc*HH + k0 + kt + bk];
            Bs[bk+0][bc] = bv.x; Bs[bk+1][bc] = bv.y;
            Bs[bk+2][bc] = bv.z; Bs[bk+3][bc] = bv.w;
        }
        __syncthreads();
        #pragma unroll
        for (int kk = 0; kk < PBK; kk++) {
            float4 a = *(const float4*)&As[kk][ty*4];
            float4 b = *(const float4*)&Bs[kk][tx*4];
            float av[4] = {a.x,a.y,a.z,a.w};
            float bv[4] = {b.x,b.y,b.z,b.w};
            #pragma unroll
            for (int i = 0; i < 4; i++)
                #pragma unroll
                for (int j = 0; j < 4; j++) acc[i][j] += av[i]*bv[j];
        }
        __syncthreads();
    }
    float* dst = g_pred_part[blockIdx.y];
    #pragma unroll
    for (int i = 0; i < 4; i++)
        #pragma unroll
        for (int j = 0; j < 4; j++)
            dst[(row0 + ty*4 + i)*VV + tx*4 + j] = acc[i][j];
}

// ================= reduce + bias + out + argmax -> next token =================
__global__ void argmax_write(float* __restrict__ out,
                             const float* __restrict__ fcb,
                             const int* __restrict__ trg,
                             const void* __restrict__ tfr,
                             int t_out)
{
    int b = blockIdx.x;
    int v = threadIdx.x;
    float acc = fcb[v];
    #pragma unroll
    for (int p = 0; p < 8; p++) acc += g_pred_part[p][b*VV + v];
    out[b*(TT*VV) + t_out*VV + v] = acc;

    __shared__ float sval[128];
    __shared__ int   sidx[128];
    sval[v] = acc; sidx[v] = v;
    __syncthreads();
    for (int s = 64; s > 0; s >>= 1) {
        if (v < s) {
            if (sval[v+s] > sval[v] ||
                (sval[v+s] == sval[v] && sidx[v+s] < sidx[v])) {
                sval[v] = sval[v+s]; sidx[v] = sidx[v+s];
            }
        }
        __syncthreads();
    }
    if (v == 0) {
        int   ti  = ((const int*)tfr)[0];
        float tfv = ((const float*)tfr)[0];
        bool tf = (ti > 0) || (tfv > 0.0f);
        g_tok[b] = tf ? trg[b*TT + t_out] : sidx[0];
    }
}

// ================= host =================
extern "C" void kernel_launch(void* const* d_in, const int* in_sizes, int n_in,
                              void* d_out, int out_size)
{
    const int*   src     = (const int*)  d_in[0];
    const int*   trg     = (const int*)  d_in[1];
    const float* emb_src = (const float*)d_in[2];
    const float* emb_trg = (const float*)d_in[3];
    const float* enc_Wih = (const float*)d_in[4];
    const float* enc_Whh = (const float*)d_in[5];
    const float* enc_bih = (const float*)d_in[6];
    const float* enc_bhh = (const float*)d_in[7];
    const float* dec_Wih = (const float*)d_in[8];
    const float* dec_Whh = (const float*)d_in[9];
    const float* dec_bih = (const float*)d_in[10];
    const float* dec_bhh = (const float*)d_in[11];
    const float* fc_W    = (const float*)d_in[12];
    const float* fc_b    = (const float*)d_in[13];
    const void*  tfr     =               d_in[14];
    float* out = (float*)d_out;

    cudaFuncSetAttribute(gru_gemm, cudaFuncAttributeMaxDynamicSharedMemorySize, SMEM_DYN);

    build_tables<<<(2*VV*G3)/256, 256>>>(emb_src, enc_Wih, enc_bih,
                                         emb_trg, dec_Wih, dec_bih);
    build_wsplit<<<(2*G3*HH)/256, 256>>>(enc_Whh, dec_Whh);
    init_kernel<<<(NB*HH)/256, 256>>>(out, trg);

    dim3 ggrid(HH/HCOL, NB/BM);   // (32, 4) = 128 blocks
    int p = 0;

    // encoder (gate fused into the GEMM)
    for (int t = 0; t < SS; t++) {
        gru_gemm<<<ggrid, THREADS, SMEM_DYN>>>(p, 0, 0, src + t, SS, enc_bhh);
        p ^= 1;
    }
    // decoder
    dim3 pgrid(NB/PBM, 8);
    dim3 pblk(32, 8);
    for (int t = 0; t < TT-1; t++) {
        gru_gemm<<<ggrid, THREADS, SMEM_DYN>>>(p, 1, 1, (const int*)nullptr, 1, dec_bhh);
        p ^= 1;
        pred_part<<<pgrid, pblk>>>(p, fc_W);
        argmax_write<<<NB, VV>>>(out, fc_b, trg, tfr, t + 1);
    }
}

// round 14
// speedup vs baseline: 1.0535x; 1.0535x over previous
#include <cuda_runtime.h>
#include <cuda_fp16.h>
#include <math.h>
#include <stdint.h>

#define NB 512
#define SS 128
#define TT 128
#define EE 128
#define HH 1024
#define VV 128
#define G3 (3*HH)

#define BM 128                     // batch rows per block
#define HCOL 32                    // h-columns per block
#define BNR 96                     // B rows per block (3 gates x 32)
#define KS 64
#define NCHUNK (HH/KS)             // 16
#define THREADS 512
#define TA_HALFS (BM*KS)           // 8192 per plane
#define TB_HALFS (BNR*KS)          // 6144 per plane
#define TA_BYTES (TA_HALFS*2)      // 16384
#define TB_BYTES (TB_HALFS*2)      // 12288
#define STAGE_BYTES (2*TA_BYTES + 2*TB_BYTES)   // 57344
#define NSTAGE 3
#define SMEM_DYN (NSTAGE*STAGE_BYTES)           // 172032
#define GHS_PITCH 100              // fp32 pitch for epilogue exchange

#define P1 (1.0f/2048.0f)
#define S1 2048.0f

// ================= device scratch =================
__device__ float g_h[2][NB*HH];                           // fp32 hidden master
__device__ __align__(16) __half g_hP[2][2][NB*HH];        // h planes, 128x64 A-tile layout
__device__ __align__(16) __half g_WP[2][2][(size_t)G3*HH];// Whh planes, gate-interleaved B-tiles
__device__ float g_Gsrc[VV*G3];
__device__ float g_Gtrg[VV*G3];
__device__ int   g_tok[NB];
__device__ float g_pred_part[8][NB*VV];

// ================= PTX helpers (portable) =================
__device__ __forceinline__ uint32_t smem_u32(const void* p) {
    uint32_t a;
    asm("{ .reg .u64 t; cvta.to.shared.u64 t, %1; cvt.u32.u64 %0, t; }" : "=r"(a) : "l"(p));
    return a;
}
#define CP16(sm, gp) \
    asm volatile("cp.async.cg.shared.global [%0], [%1], 16;" :: "r"(sm), "l"(gp) : "memory")
#define CP_COMMIT() asm volatile("cp.async.commit_group;" ::: "memory")
#define CP_WAIT1()  asm volatile("cp.async.wait_group 1;" ::: "memory")
#define CP_WAIT0()  asm volatile("cp.async.wait_group 0;" ::: "memory")
#define LDSM4(r, a) \
    asm volatile("ldmatrix.sync.aligned.m8n8.x4.shared.b16 {%0,%1,%2,%3}, [%4];" \
        : "=r"((r)[0]),"=r"((r)[1]),"=r"((r)[2]),"=r"((r)[3]) : "r"(a))
// chained MMA (in-HMMA accumulate)
#define MMA16816(d, a, b0, b1) \
    asm volatile("mma.sync.aligned.m16n8k16.row.col.f32.f16.f16.f32 " \
        "{%0,%1,%2,%3}, {%4,%5,%6,%7}, {%8,%9}, {%0,%1,%2,%3};" \
        : "+f"((d)[0]),"+f"((d)[1]),"+f"((d)[2]),"+f"((d)[3]) \
        : "r"((a)[0]),"r"((a)[1]),"r"((a)[2]),"r"((a)[3]), "r"(b0),"r"(b1))
// zero-C MMA: fresh outputs, no in-HMMA chaining
#define MMA16816_Z(d, a, b0, b1) \
    asm volatile("mma.sync.aligned.m16n8k16.row.col.f32.f16.f16.f32 " \
        "{%0,%1,%2,%3}, {%4,%5,%6,%7}, {%8,%9}, {%10,%10,%10,%10};" \
        : "=f"((d)[0]),"=f"((d)[1]),"=f"((d)[2]),"=f"((d)[3]) \
        : "r"((a)[0]),"r"((a)[1]),"r"((a)[2]),"r"((a)[3]), "r"(b0),"r"(b1), "f"(0.0f))

// swizzled half index within a tile (row pitch 128B; 16B chunk ^= row&7)
__device__ __forceinline__ int sw_half(int r, int c) {
    return r*64 + (((c>>3) ^ (r&7))<<3) + (c&7);
}
__device__ __forceinline__ uint32_t ldsm_addr(uint32_t tbase, int row, int kc) {
    return tbase + row*128 + ((((kc>>3) ^ (row&7))&7)<<4);
}
// exact 2-plane fp16 split (lo scaled by 2048 into normal range)
__device__ __forceinline__ void split2(float v, __half& h0, __half& h1) {
    h0 = __float2half(v);
    float r1 = v - __half2float(h0);
    h1 = __float2half(r1 * S1);
}

// ================= build: gi tables =================
__global__ void build_tables(const float* __restrict__ emb_src,
                             const float* __restrict__ enc_Wih,
                             const float* __restrict__ enc_bih,
                             const float* __restrict__ emb_trg,
                             const float* __restrict__ dec_Wih,
                             const float* __restrict__ dec_bih)
{
    int idx = blockIdx.x * blockDim.x + threadIdx.x;
    int which = idx / (VV*G3);
    int rem   = idx % (VV*G3);
    int v = rem / G3;
    int c = rem % G3;
    const float* emb = which ? emb_trg : emb_src;
    const float* W   = which ? dec_Wih : enc_Wih;
    const float* bi  = which ? dec_bih : enc_bih;
    float s = bi[c];
    if (v != 0) {
        const float* e = emb + v*EE;
        const float* w = W + c*EE;
        #pragma unroll 8
        for (int k = 0; k < EE; k++) s += e[k]*w[k];
    }
    float* G = which ? g_Gtrg : g_Gsrc;
    G[v*G3 + c] = s;
}

// ===== build: Whh 2-plane split, gate-interleaved B-tile layout =====
__global__ void build_wsplit(const float* __restrict__ enc_Whh,
                             const float* __restrict__ dec_Whh)
{
    int idx = blockIdx.x * blockDim.x + threadIdx.x;   // 2*3072*1024
    int dir = idx / (G3*HH);
    int rem = idx % (G3*HH);
    int n = rem / HH;          // Whh row: gate*1024 + h
    int k = rem % HH;
    const float* W = dir ? dec_Whh : enc_Whh;
    float v = W[n*HH + k];
    __half h0, h1;
    split2(v, h0, h1);
    int gate = n >> 10;
    int h    = n & 1023;
    int nt   = h >> 5;
    int trow = gate*32 + (h & 31);
    size_t pos = ((size_t)nt*NCHUNK + (k >> 6))*TB_HALFS + sw_half(trow, k & 63);
    g_WP[dir][0][pos] = h0;
    g_WP[dir][1][pos] = h1;
}

// ================= init =================
__global__ void init_kernel(float* __restrict__ out, const int* __restrict__ trg)
{
    int i = blockIdx.x * blockDim.x + threadIdx.x;
    if (i < NB*HH) {
        g_h[0][i] = 0.0f;
        g_hP[0][0][i] = __float2half(0.0f);
        g_hP[0][1][i] = __float2half(0.0f);
    }
    if (i < NB*VV) {
        int b = i / VV, v = i % VV;
        out[b*(TT*VV) + v] = 0.0f;
    }
    if (i < NB) g_tok[i] = trg[i*TT];
}

// ====== fused GRU step: gate-triple tensor GEMM + gate epilogue ======
// grid (32, 4). 512 threads (16 warps as 8m x 2n; warp tile 16m x 48 B-rows).
// Main term pair-chained per k32 (Z even-k16, chained odd-k16, RN FADD) —
// per-output arithmetic bitwise-identical to round-13 (validated numerics).
__global__ __launch_bounds__(THREADS, 1)
void gru_gemm(int pin, int dir, int table_sel,
              const int* __restrict__ ext_tok, int tok_stride,
              const float* __restrict__ bhh)
{
    extern __shared__ char smc[];
    const uint32_t sbase = smem_u32(smc);
    const int tid  = threadIdx.x;
    const int wid  = tid >> 5;
    const int lane = tid & 31;
    const int nt = blockIdx.x;           // h-col tile
    const int mt = blockIdx.y;           // m tile
    const int wm = (wid >> 1) * 16;      // warp m offset: 0..112
    const int wn = (wid & 1) * 48;       // warp B-row offset: 0/48

    const char* gA0 = (const char*)g_hP[pin][0] + (size_t)mt*NCHUNK*TA_BYTES;
    const char* gA1 = (const char*)g_hP[pin][1] + (size_t)mt*NCHUNK*TA_BYTES;
    const char* gB0 = (const char*)g_WP[dir][0] + (size_t)nt*NCHUNK*TB_BYTES;
    const char* gB1 = (const char*)g_WP[dir][1] + (size_t)nt*NCHUNK*TB_BYTES;

    float acc0[6][4], acc1[6][4];
    #pragma unroll
    for (int j = 0; j < 6; j++)
        #pragma unroll
        for (int q = 0; q < 4; q++) { acc0[j][q] = 0.0f; acc1[j][q] = 0.0f; }

    // ---- cp.async issue helper ----
    #define ISSUE_CHUNK(cc, buf) do {                                        \
        uint32_t sb = sbase + (buf)*STAGE_BYTES;                             \
        size_t goA = (size_t)(cc) * TA_BYTES;                                \
        size_t goB = (size_t)(cc) * TB_BYTES;                                \
        _Pragma("unroll")                                                    \
        for (int j = 0; j < 4; j++) {                                        \
            int u = tid + THREADS*j;             /* 0..2047 */               \
            int pl = u >> 10;                                                \
            int ln = u & 1023;                                               \
            const char* src = (pl ? gA1 : gA0) + goA + ln*16;                \
            CP16(sb + pl*TA_BYTES + ln*16, src);                             \
        }                                                                    \
        _Pragma("unroll")                                                    \
        for (int j = 0; j < 3; j++) {                                        \
            int u = tid + THREADS*j;             /* 0..1535 */               \
            int pl = (u >= 768);                                             \
            int ln = u - pl*768;                                             \
            const char* src = (pl ? gB1 : gB0) + goB + ln*16;                \
            CP16(sb + 2*TA_BYTES + pl*TB_BYTES + ln*16, src);                \
        }                                                                    \
        CP_COMMIT();                                                         \
    } while (0)

    ISSUE_CHUNK(0, 0);
    ISSUE_CHUNK(1, 1);

    const int arow  = lane & 15;
    const int khalf = (lane >> 4) * 8;

    int rbuf = 0;                        // c % 3
    for (int c = 0; c < NCHUNK; c++) {
        if (c < NCHUNK-1) { CP_WAIT1(); } else { CP_WAIT0(); }
        __syncthreads();

        const uint32_t St = sbase + rbuf*STAGE_BYTES;
        const uint32_t A0 = St;
        const uint32_t A1 = St + TA_BYTES;
        const uint32_t B0 = St + 2*TA_BYTES;
        const uint32_t B1 = B0 + TB_BYTES;

        #pragma unroll
        for (int p = 0; p < 2; p++) {        // k16-pairs: ks = 2p (even), 2p+1 (odd)
            float dt[6][4];
            // ---- even k16: fragments + Z MMAs + crosses ----
            {
                const int kc = (2*p)*16 + khalf;
                uint32_t a0[4], a1f[4];
                uint32_t b0[3][4], b1f[3][4];
                LDSM4(a0,  ldsm_addr(A0, wm + arow, kc));
                LDSM4(a1f, ldsm_addr(A1, wm + arow, kc));
                #pragma unroll
                for (int t = 0; t < 3; t++) {
                    int row = wn + t*16 + arow;
                    LDSM4(b0[t],  ldsm_addr(B0, row, kc));
                    LDSM4(b1f[t], ldsm_addr(B1, row, kc));
                }
                #pragma unroll
                for (int t = 0; t < 3; t++)
                    #pragma unroll
                    for (int s = 0; s < 2; s++) {
                        const int n8 = t*2 + s;
                        MMA16816_Z(dt[n8], a0, b0[t][s], b0[t][2+s]);
                        MMA16816(acc1[n8], a0,  b1f[t][s], b1f[t][2+s]);
                        MMA16816(acc1[n8], a1f, b0[t][s],  b0[t][2+s]);
                    }
            }
            // ---- odd k16: fragments + chained MMAs into dt + crosses ----
            {
                const int kc = (2*p+1)*16 + khalf;
                uint32_t a0[4], a1f[4];
                uint32_t b0[3][4], b1f[3][4];
                LDSM4(a0,  ldsm_addr(A0, wm + arow, kc));
                LDSM4(a1f, ldsm_addr(A1, wm + arow, kc));
                #pragma unroll
                for (int t = 0; t < 3; t++) {
                    int row = wn + t*16 + arow;
                    LDSM4(b0[t],  ldsm_addr(B0, row, kc));
                    LDSM4(b1f[t], ldsm_addr(B1, row, kc));
                }
                #pragma unroll
                for (int t = 0; t < 3; t++)
                    #pragma unroll
                    for (int s = 0; s < 2; s++) {
                        const int n8 = t*2 + s;
                        MMA16816(dt[n8], a0, b0[t][s], b0[t][2+s]);
                        MMA16816(acc1[n8], a0,  b1f[t][s], b1f[t][2+s]);
                        MMA16816(acc1[n8], a1f, b0[t][s],  b0[t][2+s]);
                    }
            }
            // ---- RN accumulate the k32 pair-sum ----
            #pragma unroll
            for (int n8 = 0; n8 < 6; n8++) {
                acc0[n8][0] += dt[n8][0];
                acc0[n8][1] += dt[n8][1];
                acc0[n8][2] += dt[n8][2];
                acc0[n8][3] += dt[n8][3];
            }
        }

        if (c + 2 < NCHUNK) {
            int wbuf = rbuf + 2; if (wbuf >= 3) wbuf -= 3;
            ISSUE_CHUNK(c+2, wbuf);
        }
        rbuf = (rbuf == 2) ? 0 : rbuf + 1;
    }
    #undef ISSUE_CHUNK

    // ---- epilogue part 1: gh -> smem exchange ----
    __syncthreads();
    float* ghs = (float*)smc;            // 128 x GHS_PITCH fp32 (51.2KB)
    {
        int erow = wm + (lane >> 2);
        #pragma unroll
        for (int n8 = 0; n8 < 6; n8++) {
            int col = wn + n8*8 + (lane & 3)*2;
            ghs[erow*GHS_PITCH + col]         = acc0[n8][0] + acc1[n8][0]*P1;
            ghs[erow*GHS_PITCH + col + 1]     = acc0[n8][1] + acc1[n8][1]*P1;
            ghs[(erow+8)*GHS_PITCH + col]     = acc0[n8][2] + acc1[n8][2]*P1;
            ghs[(erow+8)*GHS_PITCH + col + 1] = acc0[n8][3] + acc1[n8][3]*P1;
        }
    }
    __syncthreads();

    // ---- epilogue part 2: gate math + h/plane writeback ----
    const float* __restrict__ G  = table_sel ? g_Gtrg : g_Gsrc;
    const int* __restrict__ tokp = ext_tok ? ext_tok : g_tok;
    #pragma unroll
    for (int q = 0; q < 8; q++) {
        int idx = tid + THREADS*q;       // 0..4095
        int row = idx >> 5;              // 0..127
        int hc  = idx & 31;              // 0..31
        int col  = nt*32 + hc;           // global h-col
        int rowg = mt*BM + row;          // global batch row
        int tok = tokp[rowg * tok_stride];
        const float* Grow = G + (size_t)tok*G3;

        float vr = ghs[row*GHS_PITCH + hc];
        float vz = ghs[row*GHS_PITCH + 32 + hc];
        float vn = ghs[row*GHS_PITCH + 64 + hc];
        float gr = vr + bhh[col];
        float gz = vz + bhh[HH + col];
        float gn = vn + bhh[2*HH + col];
        float r = 1.0f / (1.0f + expf(-(Grow[col]      + gr)));
        float z = 1.0f / (1.0f + expf(-(Grow[HH + col] + gz)));
        float n = tanhf(Grow[2*HH + col] + r * gn);
        float hp = g_h[pin][rowg*HH + col];
        float ho = (1.0f - z)*n + z*hp;

        g_h[pin ^ 1][rowg*HH + col] = ho;
        __half h0, h1;
        split2(ho, h0, h1);
        size_t pos = ((size_t)(rowg >> 7)*NCHUNK + (col >> 6))*TA_HALFS
                   + sw_half(rowg & 127, col & 63);
        g_hP[pin ^ 1][0][pos] = h0;
        g_hP[pin ^ 1][1][pos] = h1;
    }
}

// ================= decoder pred GEMM (split-K SIMT, fp32) =================
#define PBM 32
#define PBK 16
__global__ __launch_bounds__(256, 1)
void pred_part(int pcur, const float* __restrict__ fcW)
{
    const float* __restrict__ h = g_h[pcur];
    __shared__ float As[PBK][PBM+4];
    __shared__ float Bs[PBK][VV+4];

    const int row0 = blockIdx.x * PBM;
    const int k0   = blockIdx.y * (HH/8);
    const int tx = threadIdx.x, ty = threadIdx.y;
    const int tid = ty*32 + tx;

    float acc[4][4];
    #pragma unroll
    for (int i = 0; i < 4; i++)
        #pragma unroll
        for (int j = 0; j < 4; j++) acc[i][j] = 0.0f;

    for (int kt = 0; kt < HH/8; kt += PBK) {
        if (tid < 128) {
            int ar = tid >> 2;
            int ak = (tid & 3) << 2;
            float4 av = *(const float4*)&h[(row0+ar)*HH + k0 + kt + ak];
            As[ak+0][ar] = av.x; As[ak+1][ar] = av.y;
            As[ak+2][ar] = av.z; As[ak+3][ar] = av.w;
        }
        #pragma unroll
        for (int l = 0; l < 2; l++) {
            int t2 = l*256 + tid;
            int bc = t2 >> 2;
            int bk = (t2 & 3) << 2;
            float4 bv = *(const float4*)&fcW[bc*HH + k0 + kt + bk];
            Bs[bk+0][bc] = bv.x; Bs[bk+1][bc] = bv.y;
            Bs[bk+2][bc] = bv.z; Bs[bk+3][bc] = bv.w;
        }
        __syncthreads();
        #pragma unroll
        for (int kk = 0; kk < PBK; kk++) {
            float4 a = *(const float4*)&As[kk][ty*4];
            float4 b = *(const float4*)&Bs[kk][tx*4];
            float av[4] = {a.x,a.y,a.z,a.w};
            float bv[4] = {b.x,b.y,b.z,b.w};
            #pragma unroll
            for (int i = 0; i < 4; i++)
                #pragma unroll
                for (int j = 0; j < 4; j++) acc[i][j] += av[i]*bv[j];
        }
        __syncthreads();
    }
    float* dst = g_pred_part[blockIdx.y];
    #pragma unroll
    for (int i = 0; i < 4; i++)
        #pragma unroll
        for (int j = 0; j < 4; j++)
            dst[(row0 + ty*4 + i)*VV + tx*4 + j] = acc[i][j];
}

// ================= reduce + bias + out + argmax -> next token =================
__global__ void argmax_write(float* __restrict__ out,
                             const float* __restrict__ fcb,
                             const int* __restrict__ trg,
                             const void* __restrict__ tfr,
                             int t_out)
{
    int b = blockIdx.x;
    int v = threadIdx.x;
    float acc = fcb[v];
    #pragma unroll
    for (int p = 0; p < 8; p++) acc += g_pred_part[p][b*VV + v];
    out[b*(TT*VV) + t_out*VV + v] = acc;

    __shared__ float sval[128];
    __shared__ int   sidx[128];
    sval[v] = acc; sidx[v] = v;
    __syncthreads();
    for (int s = 64; s > 0; s >>= 1) {
        if (v < s) {
            if (sval[v+s] > sval[v] ||
                (sval[v+s] == sval[v] && sidx[v+s] < sidx[v])) {
                sval[v] = sval[v+s]; sidx[v] = sidx[v+s];
            }
        }
        __syncthreads();
    }
    if (v == 0) {
        int   ti  = ((const int*)tfr)[0];
        float tfv = ((const float*)tfr)[0];
        bool tf = (ti > 0) || (tfv > 0.0f);
        g_tok[b] = tf ? trg[b*TT + t_out] : sidx[0];
    }
}

// ================= host =================
extern "C" void kernel_launch(void* const* d_in, const int* in_sizes, int n_in,
                              void* d_out, int out_size)
{
    const int*   src     = (const int*)  d_in[0];
    const int*   trg     = (const int*)  d_in[1];
    const float* emb_src = (const float*)d_in[2];
    const float* emb_trg = (const float*)d_in[3];
    const float* enc_Wih = (const float*)d_in[4];
    const float* enc_Whh = (const float*)d_in[5];
    const float* enc_bih = (const float*)d_in[6];
    const float* enc_bhh = (const float*)d_in[7];
    const float* dec_Wih = (const float*)d_in[8];
    const float* dec_Whh = (const float*)d_in[9];
    const float* dec_bih = (const float*)d_in[10];
    const float* dec_bhh = (const float*)d_in[11];
    const float* fc_W    = (const float*)d_in[12];
    const float* fc_b    = (const float*)d_in[13];
    const void*  tfr     =               d_in[14];
    float* out = (float*)d_out;

    cudaFuncSetAttribute(gru_gemm, cudaFuncAttributeMaxDynamicSharedMemorySize, SMEM_DYN);

    build_tables<<<(2*VV*G3)/256, 256>>>(emb_src, enc_Wih, enc_bih,
                                         emb_trg, dec_Wih, dec_bih);
    build_wsplit<<<(2*G3*HH)/256, 256>>>(enc_Whh, dec_Whh);
    init_kernel<<<(NB*HH)/256, 256>>>(out, trg);

    dim3 ggrid(HH/HCOL, NB/BM);   // (32, 4) = 128 blocks
    int p = 0;

    // encoder (gate fused into the GEMM)
    for (int t = 0; t < SS; t++) {
        gru_gemm<<<ggrid, THREADS, SMEM_DYN>>>(p, 0, 0, src + t, SS, enc_bhh);
        p ^= 1;
    }
    // decoder
    dim3 pgrid(NB/PBM, 8);
    dim3 pblk(32, 8);
    for (int t = 0; t < TT-1; t++) {
        gru_gemm<<<ggrid, THREADS, SMEM_DYN>>>(p, 1, 1, (const int*)nullptr, 1, dec_bhh);
        p ^= 1;
        pred_part<<<pgrid, pblk>>>(p, fc_W);
        argmax_write<<<NB, VV>>>(out, fc_b, trg, tfr, t + 1);
    }
}